// round 5
// baseline (speedup 1.0000x reference)
#include <cuda_runtime.h>
#include <math.h>

// Problem constants
#define Dm    1024
#define Sseq  2048
#define Bb    4
#define Hh    16
#define HD    64
#define NT    (Bb * Sseq)   // 8192 tokens

// ---------------- scratch (module-static device memory; no runtime alloc) ---
__device__ float g_xp[NT * Dm];
__device__ float g_q [NT * Dm];
__device__ float g_k [NT * Dm];
__device__ float g_v [NT * Dm];
__device__ float g_o [NT * Dm];
__device__ float g_h [NT * Dm];

// ---------------- tf32 mma helpers -----------------------------------------
__device__ __forceinline__ unsigned f2tf(float f) {
    unsigned r;
    asm("cvt.rna.tf32.f32 %0, %1;" : "=r"(r) : "f"(f));
    return r;
}

__device__ __forceinline__ void mma8(
    float& c0, float& c1, float& c2, float& c3,
    unsigned a0, unsigned a1, unsigned a2, unsigned a3,
    unsigned b0, unsigned b1)
{
    asm volatile(
        "mma.sync.aligned.m16n8k8.row.col.f32.tf32.tf32.f32 "
        "{%0,%1,%2,%3}, {%4,%5,%6,%7}, {%8,%9}, {%0,%1,%2,%3};"
        : "+f"(c0), "+f"(c1), "+f"(c2), "+f"(c3)
        : "r"(a0), "r"(a1), "r"(a2), "r"(a3), "r"(b0), "r"(b1));
}

// ============================================================================
// Kernel 1: xp = x + pe
// ============================================================================
__global__ __launch_bounds__(256) void add_pe_kernel(
    const float* __restrict__ x, const float* __restrict__ pe,
    float* __restrict__ xp)
{
    int idx = blockIdx.x * 256 + threadIdx.x;
    int e = idx * 4;
    int t = e >> 10;
    int c = e & 1023;
    int s = t & (Sseq - 1);
    float4 xv = *reinterpret_cast<const float4*>(x + e);
    float4 pv = *reinterpret_cast<const float4*>(pe + s * Dm + c);
    xv.x += pv.x; xv.y += pv.y; xv.z += pv.z; xv.w += pv.w;
    *reinterpret_cast<float4*>(xp + e) = xv;
}

// ============================================================================
// Kernel 2: tf32 GEMM with fragment-packed smem + software pipeline.
//   Tile 128x128x32, 8 warps, warp tile 64x32.
//   Smem holds tf32 bits already laid out per-lane in mma fragment order:
//     A_frag[ks(4)][mt(8)][lane(32)] : uint4  (a0,a1,a2,a3)
//     B_frag[ks(4)][nt(16)][lane(32)]: uint2  (b0,b1)
//   Inner loop is pure LDS.128/LDS.64 + MMA (contiguous -> conflict-free).
// ============================================================================
__global__ __launch_bounds__(256, 2) void gemm_tc(
    const float* __restrict__ A, const float* __restrict__ W,
    const float* __restrict__ bias, const float* __restrict__ resid,
    float* __restrict__ out, int mode)
{
    __shared__ uint4 As4[2][1024];   // 2 x 16KB
    __shared__ uint2 Bs2[2][2048];   // 2 x 16KB

    int tid  = threadIdx.x;
    int lane = tid & 31;
    int warp = tid >> 5;
    int g    = lane >> 2;
    int tig  = lane & 3;
    int wm   = warp & 1;
    int wn   = warp >> 1;
    int m0   = blockIdx.y * 128;
    int n0   = blockIdx.x * 128;

    float acc[4][4][4];
#pragma unroll
    for (int i = 0; i < 4; i++)
#pragma unroll
        for (int j = 0; j < 4; j++)
#pragma unroll
            for (int r = 0; r < 4; r++) acc[i][j][r] = 0.0f;

    unsigned a_ld[16], b_ld[16];

    // fragment-gather load of one K-chunk into registers (pre-converted)
#define GLOAD(K0)                                                              \
    {                                                                          \
        _Pragma("unroll")                                                      \
        for (int i = 0; i < 4; i++) {                                          \
            int f  = tid + 256 * i;                                            \
            int la = f & 31, mt = (f >> 5) & 7, ks = f >> 8;                   \
            int row = m0 + mt * 16 + (la >> 2);                                \
            int kk  = (K0) + ks * 8 + (la & 3);                                \
            const float* p = A + (size_t)row * 1024 + kk;                      \
            a_ld[4*i+0] = f2tf(p[0]);                                          \
            a_ld[4*i+1] = f2tf(p[8192]);                                       \
            a_ld[4*i+2] = f2tf(p[4]);                                          \
            a_ld[4*i+3] = f2tf(p[8196]);                                       \
        }                                                                      \
        _Pragma("unroll")                                                      \
        for (int i = 0; i < 8; i++) {                                          \
            int f  = tid + 256 * i;                                            \
            int la = f & 31, nt = (f >> 5) & 15, ks = f >> 9;                  \
            int col = n0 + nt * 8 + (la >> 2);                                 \
            int kk  = (K0) + ks * 8 + (la & 3);                                \
            const float* p = W + (size_t)kk * 1024 + col;                      \
            b_ld[2*i+0] = f2tf(p[0]);                                          \
            b_ld[2*i+1] = f2tf(p[4096]);                                       \
        }                                                                      \
    }

    GLOAD(0);

    for (int it = 0; it < 32; ++it) {
        int p = it & 1;
        // store staged fragments
#pragma unroll
        for (int i = 0; i < 4; i++)
            As4[p][tid + 256 * i] = make_uint4(a_ld[4*i], a_ld[4*i+1], a_ld[4*i+2], a_ld[4*i+3]);
#pragma unroll
        for (int i = 0; i < 8; i++)
            Bs2[p][tid + 256 * i] = make_uint2(b_ld[2*i], b_ld[2*i+1]);
        __syncthreads();

        if (it < 31) GLOAD((it + 1) * 32);   // in flight under the MMAs

#pragma unroll
        for (int ks = 0; ks < 4; ks++) {
            uint4 a[4];
            uint2 b[4];
#pragma unroll
            for (int mt = 0; mt < 4; mt++)
                a[mt] = As4[p][(ks * 8 + wm * 4 + mt) * 32 + lane];
#pragma unroll
            for (int nt = 0; nt < 4; nt++)
                b[nt] = Bs2[p][(ks * 16 + wn * 4 + nt) * 32 + lane];
#pragma unroll
            for (int mt = 0; mt < 4; mt++)
#pragma unroll
                for (int nt = 0; nt < 4; nt++)
                    mma8(acc[mt][nt][0], acc[mt][nt][1], acc[mt][nt][2], acc[mt][nt][3],
                         a[mt].x, a[mt].y, a[mt].z, a[mt].w, b[nt].x, b[nt].y);
        }
    }
#undef GLOAD

    // epilogue
#pragma unroll
    for (int mt = 0; mt < 4; mt++) {
        int r0 = m0 + wm * 64 + mt * 16 + g;
#pragma unroll
        for (int nt = 0; nt < 4; nt++) {
            int c = n0 + wn * 32 + nt * 8 + 2 * tig;
            float2 bv = *reinterpret_cast<const float2*>(bias + c);
            float2 lo = make_float2(acc[mt][nt][0] + bv.x, acc[mt][nt][1] + bv.y);
            float2 hi = make_float2(acc[mt][nt][2] + bv.x, acc[mt][nt][3] + bv.y);
            if (mode == 1) {
                float2 rl = *reinterpret_cast<const float2*>(resid + (size_t)r0 * Dm + c);
                float2 rh = *reinterpret_cast<const float2*>(resid + (size_t)(r0 + 8) * Dm + c);
                lo.x += rl.x; lo.y += rl.y;
                hi.x += rh.x; hi.y += rh.y;
                *reinterpret_cast<float2*>(out + (size_t)r0 * Dm + c) = lo;
                *reinterpret_cast<float2*>(out + (size_t)(r0 + 8) * Dm + c) = hi;
            } else {
                int h = c >> 6, d = c & 63;
                int b0 = r0 >> 11, s0 = r0 & (Sseq - 1);
                size_t o0 = (((size_t)(b0 * Hh + h) * Sseq) + s0) * HD + d;
                size_t o1 = o0 + 8 * HD;
                *reinterpret_cast<float2*>(out + o0) = lo;
                *reinterpret_cast<float2*>(out + o1) = hi;
            }
        }
    }
}

// ============================================================================
// Kernel 3: flash attention, tf32 mma, fragment-packed operands.
//   128-query x 64-key tiles; warp w owns query rows [w*16, w*16+16).
//   Qf: A-frags [ks(8)][mt(8)][lane] uint4   (packed once per block)
//   Kf: B-frags [ks(8)][nt(8)][lane] uint2   (ks over headdim)
//   Vf: B-frags [ks(8)][ht(8)][lane] uint2   (ks over key dim)
//   Ps: [128][68] tf32 bits (scalar reads, pad 68 == 4 mod 32 -> no conflicts)
// ============================================================================
#define ATTN_SMEM_UINTS (8192 + 4096 + 4096 + 128 * 68)

__global__ __launch_bounds__(256, 2) void attn_tc(
    const float* __restrict__ Q, const float* __restrict__ K,
    const float* __restrict__ V, float* __restrict__ O)
{
    extern __shared__ unsigned usm[];
    unsigned* Qf = usm;             // 8192 uints
    unsigned* Kf = Qf + 8192;       // 4096
    unsigned* Vf = Kf + 4096;       // 4096
    unsigned* Ps = Vf + 4096;       // 8704

    int tid  = threadIdx.x;
    int lane = tid & 31;
    int warp = tid >> 5;
    int g    = lane >> 2;
    int tig  = lane & 3;
    int bh   = blockIdx.y;
    int q0   = blockIdx.x * 128;
    int qrow = warp * 16 + g;

    const float* Qb = Q + (size_t)bh * Sseq * HD;
    const float* Kb = K + (size_t)bh * Sseq * HD;
    const float* Vb = V + (size_t)bh * Sseq * HD;

    // pack Q tile into A-fragments (scaled by 1/sqrt(64), pre-converted)
#pragma unroll
    for (int i = 0; i < 8; i++) {
        int f  = tid + 256 * i;              // 0..2047
        int la = f & 31, mt = (f >> 5) & 7, ks = f >> 8;
        int row = q0 + mt * 16 + (la >> 2);
        int d   = ks * 8 + (la & 3);
        const float* p = Qb + (size_t)row * HD + d;
        uint4 v;
        v.x = f2tf(p[0]   * 0.125f);
        v.y = f2tf(p[512] * 0.125f);   // row+8
        v.z = f2tf(p[4]   * 0.125f);
        v.w = f2tf(p[516] * 0.125f);
        reinterpret_cast<uint4*>(Qf)[f] = v;
    }

    float m0r = -1e30f, m1r = -1e30f, l0 = 0.0f, l1 = 0.0f;
    float o[8][4];
#pragma unroll
    for (int i = 0; i < 8; i++)
#pragma unroll
        for (int j = 0; j < 4; j++) o[i][j] = 0.0f;

    for (int kt = 0; kt < Sseq / 64; kt++) {
        int k0 = kt * 64;
        // pack K and V tiles into B-fragments
#pragma unroll
        for (int i = 0; i < 8; i++) {
            int f  = tid + 256 * i;
            int la = f & 31, nt = (f >> 5) & 7, ks = f >> 8;
            int g2 = la >> 2, t2 = la & 3;
            const float* pk = Kb + (size_t)(k0 + nt * 8 + g2) * HD + ks * 8 + t2;
            reinterpret_cast<uint2*>(Kf)[f] = make_uint2(f2tf(pk[0]), f2tf(pk[4]));
            const float* pv = Vb + (size_t)(k0 + ks * 8 + t2) * HD + nt * 8 + g2;
            reinterpret_cast<uint2*>(Vf)[f] = make_uint2(f2tf(pv[0]), f2tf(pv[256]));
        }
        __syncthreads();

        // S = Q @ K^T
        float s[8][4];
#pragma unroll
        for (int nt = 0; nt < 8; nt++)
#pragma unroll
            for (int j = 0; j < 4; j++) s[nt][j] = 0.0f;

#pragma unroll
        for (int ks = 0; ks < 8; ks++) {
            uint4 a = reinterpret_cast<const uint4*>(Qf)[(ks * 8 + warp) * 32 + lane];
#pragma unroll
            for (int nt = 0; nt < 8; nt++) {
                uint2 b = reinterpret_cast<const uint2*>(Kf)[(ks * 8 + nt) * 32 + lane];
                mma8(s[nt][0], s[nt][1], s[nt][2], s[nt][3], a.x, a.y, a.z, a.w, b.x, b.y);
            }
        }

        // online softmax (rows qrow, qrow+8; reduce over 4-lane quad)
        float rmax0 = -1e30f, rmax1 = -1e30f;
#pragma unroll
        for (int nt = 0; nt < 8; nt++) {
            rmax0 = fmaxf(rmax0, fmaxf(s[nt][0], s[nt][1]));
            rmax1 = fmaxf(rmax1, fmaxf(s[nt][2], s[nt][3]));
        }
        rmax0 = fmaxf(rmax0, __shfl_xor_sync(0xffffffffu, rmax0, 1));
        rmax0 = fmaxf(rmax0, __shfl_xor_sync(0xffffffffu, rmax0, 2));
        rmax1 = fmaxf(rmax1, __shfl_xor_sync(0xffffffffu, rmax1, 1));
        rmax1 = fmaxf(rmax1, __shfl_xor_sync(0xffffffffu, rmax1, 2));
        float mn0 = fmaxf(m0r, rmax0), mn1 = fmaxf(m1r, rmax1);
        float cf0 = __expf(m0r - mn0), cf1 = __expf(m1r - mn1);
        m0r = mn0; m1r = mn1;
        float rs0 = 0.0f, rs1 = 0.0f;
#pragma unroll
        for (int nt = 0; nt < 8; nt++) {
            s[nt][0] = __expf(s[nt][0] - mn0);
            s[nt][1] = __expf(s[nt][1] - mn0);
            s[nt][2] = __expf(s[nt][2] - mn1);
            s[nt][3] = __expf(s[nt][3] - mn1);
            rs0 += s[nt][0] + s[nt][1];
            rs1 += s[nt][2] + s[nt][3];
        }
        rs0 += __shfl_xor_sync(0xffffffffu, rs0, 1);
        rs0 += __shfl_xor_sync(0xffffffffu, rs0, 2);
        rs1 += __shfl_xor_sync(0xffffffffu, rs1, 1);
        rs1 += __shfl_xor_sync(0xffffffffu, rs1, 2);
        l0 = l0 * cf0 + rs0;
        l1 = l1 * cf1 + rs1;
#pragma unroll
        for (int ht = 0; ht < 8; ht++) {
            o[ht][0] *= cf0; o[ht][1] *= cf0;
            o[ht][2] *= cf1; o[ht][3] *= cf1;
        }
        // park P as tf32 bits (each warp touches only its own 16 rows)
#pragma unroll
        for (int nt = 0; nt < 8; nt++) {
            *reinterpret_cast<uint2*>(&Ps[(qrow    ) * 68 + nt * 8 + 2 * tig]) =
                make_uint2(f2tf(s[nt][0]), f2tf(s[nt][1]));
            *reinterpret_cast<uint2*>(&Ps[(qrow + 8) * 68 + nt * 8 + 2 * tig]) =
                make_uint2(f2tf(s[nt][2]), f2tf(s[nt][3]));
        }
        __syncwarp();

        // O += P @ V
#pragma unroll
        for (int ks = 0; ks < 8; ks++) {
            int kc = ks * 8;
            unsigned a0 = Ps[(qrow    ) * 68 + kc + tig];
            unsigned a1 = Ps[(qrow + 8) * 68 + kc + tig];
            unsigned a2 = Ps[(qrow    ) * 68 + kc + tig + 4];
            unsigned a3 = Ps[(qrow + 8) * 68 + kc + tig + 4];
#pragma unroll
            for (int ht = 0; ht < 8; ht++) {
                uint2 b = reinterpret_cast<const uint2*>(Vf)[(ks * 8 + ht) * 32 + lane];
                mma8(o[ht][0], o[ht][1], o[ht][2], o[ht][3], a0, a1, a2, a3, b.x, b.y);
            }
        }
        __syncthreads();
    }

    // epilogue: normalize, store token-major
    int b = bh >> 4, h = bh & 15;
    int tok0 = b * Sseq + q0 + qrow;
    float inv0 = 1.0f / l0, inv1 = 1.0f / l1;
#pragma unroll
    for (int ht = 0; ht < 8; ht++) {
        int col = h * HD + ht * 8 + 2 * tig;
        *reinterpret_cast<float2*>(O + (size_t)tok0 * Dm + col) =
            make_float2(o[ht][0] * inv0, o[ht][1] * inv0);
        *reinterpret_cast<float2*>(O + (size_t)(tok0 + 8) * Dm + col) =
            make_float2(o[ht][2] * inv1, o[ht][3] * inv1);
    }
}

// ============================================================================
// Kernel 4: LayerNorm per token
// ============================================================================
__global__ __launch_bounds__(256) void ln_kernel(
    const float* __restrict__ hb, const float* __restrict__ gamma,
    const float* __restrict__ beta, float* __restrict__ out)
{
    int t = blockIdx.x;
    int tid = threadIdx.x;
    __shared__ float red[8];

    float4 v = reinterpret_cast<const float4*>(hb + (size_t)t * Dm)[tid];

    float s = v.x + v.y + v.z + v.w;
    for (int off = 16; off; off >>= 1) s += __shfl_xor_sync(0xffffffffu, s, off);
    if ((tid & 31) == 0) red[tid >> 5] = s;
    __syncthreads();
    float tot = 0.0f;
#pragma unroll
    for (int i = 0; i < 8; i++) tot += red[i];
    float mu = tot * (1.0f / Dm);
    __syncthreads();

    float dx = v.x - mu, dy = v.y - mu, dz = v.z - mu, dw = v.w - mu;
    float sq = dx * dx + dy * dy + dz * dz + dw * dw;
    for (int off = 16; off; off >>= 1) sq += __shfl_xor_sync(0xffffffffu, sq, off);
    if ((tid & 31) == 0) red[tid >> 5] = sq;
    __syncthreads();
    float vtot = 0.0f;
#pragma unroll
    for (int i = 0; i < 8; i++) vtot += red[i];
    float rsd = rsqrtf(vtot * (1.0f / Dm) + 1e-5f);

    int c = tid * 4;
    float4 gm = *reinterpret_cast<const float4*>(gamma + c);
    float4 bt = *reinterpret_cast<const float4*>(beta + c);
    float4 r;
    r.x = dx * rsd * gm.x + bt.x;
    r.y = dy * rsd * gm.y + bt.y;
    r.z = dz * rsd * gm.z + bt.z;
    r.w = dw * rsd * gm.w + bt.w;
    reinterpret_cast<float4*>(out + (size_t)t * Dm)[tid] = r;
}

// ============================================================================
// launch
// ============================================================================
extern "C" void kernel_launch(void* const* d_in, const int* in_sizes, int n_in,
                              void* d_out, int out_size)
{
    const float* x     = (const float*)d_in[0];
    const float* wq    = (const float*)d_in[1];
    const float* bq    = (const float*)d_in[2];
    const float* wk    = (const float*)d_in[3];
    const float* bk    = (const float*)d_in[4];
    const float* wv    = (const float*)d_in[5];
    const float* bv    = (const float*)d_in[6];
    const float* wo    = (const float*)d_in[7];
    const float* bo    = (const float*)d_in[8];
    const float* gamma = (const float*)d_in[9];
    const float* beta  = (const float*)d_in[10];
    const float* pe    = (const float*)d_in[11];
    float* out = (float*)d_out;

    float *xp, *q, *k, *v, *o, *hb;
    cudaGetSymbolAddress((void**)&xp, g_xp);
    cudaGetSymbolAddress((void**)&q,  g_q);
    cudaGetSymbolAddress((void**)&k,  g_k);
    cudaGetSymbolAddress((void**)&v,  g_v);
    cudaGetSymbolAddress((void**)&o,  g_o);
    cudaGetSymbolAddress((void**)&hb, g_h);

    static const int attn_smem = ATTN_SMEM_UINTS * 4;
    cudaFuncSetAttribute(attn_tc, cudaFuncAttributeMaxDynamicSharedMemorySize, attn_smem);

    // 1. x + pe
    add_pe_kernel<<<(NT * Dm) / (256 * 4), 256>>>(x, pe, xp);

    // 2. Q, K, V projections
    dim3 gemm_grid(Dm / 128, NT / 128);   // (8, 64)
    gemm_tc<<<gemm_grid, 256>>>(xp, wq, bq, nullptr, q, 0);
    gemm_tc<<<gemm_grid, 256>>>(xp, wk, bk, nullptr, k, 0);
    gemm_tc<<<gemm_grid, 256>>>(xp, wv, bv, nullptr, v, 0);

    // 3. flash attention
    dim3 attn_grid(Sseq / 128, Bb * Hh);  // (16, 64)
    attn_tc<<<attn_grid, 256, attn_smem>>>(q, k, v, o);

    // 4. output projection + residual
    gemm_tc<<<gemm_grid, 256>>>(o, wo, bo, xp, hb, 1);

    // 5. layernorm
    ln_kernel<<<NT, 256>>>(hb, gamma, beta, out);
}

// round 6
// speedup vs baseline: 1.8164x; 1.8164x over previous
#include <cuda_runtime.h>
#include <cuda_fp16.h>
#include <math.h>

// Problem constants
#define Dm    1024
#define Sseq  2048
#define Bb    4
#define Hh    16
#define HD    64
#define NT    (Bb * Sseq)   // 8192 tokens

// ---------------- scratch (module-static device memory) --------------------
__device__ float  g_xp [NT * Dm];      // x + pe fp32 (residual)
__device__ __half g_xph[NT * Dm];      // x + pe fp16 (GEMM A)
__device__ __half g_wh [4 * Dm * Dm];  // wq,wk,wv,wo fp16
__device__ __half g_qh [NT * Dm];      // Q  [bh][s][hd] fp16
__device__ __half g_kh [NT * Dm];
__device__ __half g_vh [NT * Dm];
__device__ __half g_oh [NT * Dm];      // attn out [token][D] fp16
__device__ float  g_h  [NT * Dm];      // pre-LN fp32

// ---------------- PTX helpers ----------------------------------------------
__device__ __forceinline__ unsigned sptr(const void* p) {
    return (unsigned)__cvta_generic_to_shared(p);
}

#define CP16(dst, src) \
    asm volatile("cp.async.cg.shared.global [%0], [%1], 16;" :: "r"(dst), "l"(src))
#define CP_COMMIT() asm volatile("cp.async.commit_group;")
#define CP_WAIT0()  asm volatile("cp.async.wait_group 0;")

__device__ __forceinline__ void ldsm4(unsigned& r0, unsigned& r1, unsigned& r2, unsigned& r3,
                                      unsigned addr) {
    asm volatile("ldmatrix.sync.aligned.m8n8.x4.shared.b16 {%0,%1,%2,%3}, [%4];"
        : "=r"(r0), "=r"(r1), "=r"(r2), "=r"(r3) : "r"(addr));
}
__device__ __forceinline__ void ldsm4t(unsigned& r0, unsigned& r1, unsigned& r2, unsigned& r3,
                                       unsigned addr) {
    asm volatile("ldmatrix.sync.aligned.m8n8.x4.trans.shared.b16 {%0,%1,%2,%3}, [%4];"
        : "=r"(r0), "=r"(r1), "=r"(r2), "=r"(r3) : "r"(addr));
}
__device__ __forceinline__ void hmma(float& c0, float& c1, float& c2, float& c3,
                                     unsigned a0, unsigned a1, unsigned a2, unsigned a3,
                                     unsigned b0, unsigned b1) {
    asm volatile(
        "mma.sync.aligned.m16n8k16.row.col.f32.f16.f16.f32 "
        "{%0,%1,%2,%3}, {%4,%5,%6,%7}, {%8,%9}, {%0,%1,%2,%3};"
        : "+f"(c0), "+f"(c1), "+f"(c2), "+f"(c3)
        : "r"(a0), "r"(a1), "r"(a2), "r"(a3), "r"(b0), "r"(b1));
}

// ============================================================================
// Kernel 1: xp = x + pe, write fp32 + fp16
// ============================================================================
__global__ __launch_bounds__(256) void add_pe_kernel(
    const float* __restrict__ x, const float* __restrict__ pe,
    float* __restrict__ xp, __half* __restrict__ xph)
{
    int idx = blockIdx.x * 256 + threadIdx.x;
    int e = idx * 4;
    int t = e >> 10;
    int c = e & 1023;
    int s = t & (Sseq - 1);
    float4 xv = *reinterpret_cast<const float4*>(x + e);
    float4 pv = *reinterpret_cast<const float4*>(pe + s * Dm + c);
    xv.x += pv.x; xv.y += pv.y; xv.z += pv.z; xv.w += pv.w;
    *reinterpret_cast<float4*>(xp + e) = xv;
    __half2 h0 = __floats2half2_rn(xv.x, xv.y);
    __half2 h1 = __floats2half2_rn(xv.z, xv.w);
    *reinterpret_cast<__half2*>(xph + e)     = h0;
    *reinterpret_cast<__half2*>(xph + e + 2) = h1;
}

// fp32 -> fp16 conversion (weights), 8 elements/thread
__global__ __launch_bounds__(256) void cvt_kernel(
    const float* __restrict__ in, __half* __restrict__ out)
{
    int i = (blockIdx.x * 256 + threadIdx.x) * 8;
    float4 a = *reinterpret_cast<const float4*>(in + i);
    float4 b = *reinterpret_cast<const float4*>(in + i + 4);
    __half2 h0 = __floats2half2_rn(a.x, a.y);
    __half2 h1 = __floats2half2_rn(a.z, a.w);
    __half2 h2 = __floats2half2_rn(b.x, b.y);
    __half2 h3 = __floats2half2_rn(b.z, b.w);
    uint4 pk;
    pk.x = *reinterpret_cast<unsigned*>(&h0);
    pk.y = *reinterpret_cast<unsigned*>(&h1);
    pk.z = *reinterpret_cast<unsigned*>(&h2);
    pk.w = *reinterpret_cast<unsigned*>(&h3);
    *reinterpret_cast<uint4*>(out + i) = pk;
}

// ============================================================================
// Kernel 2: fp16 GEMM  out[8192,1024] = A @ W + bias
//   128x128x32 tile, 8 warps (warp 64x32), cp.async double-buffered staging,
//   ldmatrix operand loads, mma.m16n8k16.
//   As rows padded to 40 halves (80B), Bs rows to 136 halves (272B):
//   LDSM 8-row phases hit 8 distinct bank quads -> conflict-free.
//   mode 0: fp16 scatter to [b,h,s,hd]; mode 1: fp32 token-major + residual.
// ============================================================================
__global__ __launch_bounds__(256, 2) void gemm_h(
    const __half* __restrict__ A, const __half* __restrict__ W,
    const float* __restrict__ bias, const float* __restrict__ resid,
    __half* __restrict__ outh, float* __restrict__ outf, int mode)
{
    __shared__ __align__(16) __half As[2][128 * 40];
    __shared__ __align__(16) __half Bs[2][32 * 136];

    int tid  = threadIdx.x;
    int lane = tid & 31;
    int warp = tid >> 5;
    int g    = lane >> 2;
    int tig  = lane & 3;
    int wm   = warp & 1;
    int wn   = warp >> 1;
    int m0   = blockIdx.y * 128;
    int n0   = blockIdx.x * 128;

    float acc[4][4][4];
#pragma unroll
    for (int i = 0; i < 4; i++)
#pragma unroll
        for (int j = 0; j < 4; j++)
#pragma unroll
            for (int r = 0; r < 4; r++) acc[i][j][r] = 0.0f;

#define STAGE(IT, P)                                                           \
    {                                                                          \
        int kk0 = (IT) * 32;                                                   \
        _Pragma("unroll")                                                      \
        for (int i = 0; i < 2; i++) {                                          \
            int f = tid + 256 * i;                                             \
            int row = f >> 2, c = f & 3;                                       \
            CP16(sptr(&As[P][row * 40 + c * 8]),                               \
                 A + (size_t)(m0 + row) * 1024 + kk0 + c * 8);                 \
        }                                                                      \
        _Pragma("unroll")                                                      \
        for (int i = 0; i < 2; i++) {                                          \
            int f = tid + 256 * i;                                             \
            int row = f >> 4, c = f & 15;                                      \
            CP16(sptr(&Bs[P][row * 136 + c * 8]),                              \
                 W + (size_t)(kk0 + row) * 1024 + n0 + c * 8);                 \
        }                                                                      \
        CP_COMMIT();                                                           \
    }

    STAGE(0, 0);

    for (int it = 0; it < 32; ++it) {
        int p = it & 1;
        CP_WAIT0();
        __syncthreads();
        if (it < 31) STAGE(it + 1, p ^ 1);

        unsigned a_base = sptr(&As[p][(wm * 64 + (lane & 15)) * 40 + (lane >> 4) * 8]);
        unsigned b_base = sptr(&Bs[p][(lane & 15) * 136 + wn * 32 + (lane >> 4) * 8]);
#pragma unroll
        for (int ks = 0; ks < 2; ks++) {
            unsigned a[4][4];
#pragma unroll
            for (int mt = 0; mt < 4; mt++)
                ldsm4(a[mt][0], a[mt][1], a[mt][2], a[mt][3],
                      a_base + (mt * 16 * 40 + ks * 16) * 2);
#pragma unroll
            for (int j = 0; j < 2; j++) {
                unsigned r0, r1, r2, r3;
                ldsm4t(r0, r1, r2, r3, b_base + (ks * 16 * 136 + j * 16) * 2);
#pragma unroll
                for (int mt = 0; mt < 4; mt++) {
                    hmma(acc[mt][2*j][0], acc[mt][2*j][1], acc[mt][2*j][2], acc[mt][2*j][3],
                         a[mt][0], a[mt][1], a[mt][2], a[mt][3], r0, r1);
                    hmma(acc[mt][2*j+1][0], acc[mt][2*j+1][1], acc[mt][2*j+1][2], acc[mt][2*j+1][3],
                         a[mt][0], a[mt][1], a[mt][2], a[mt][3], r2, r3);
                }
            }
        }
    }
#undef STAGE

    // epilogue
#pragma unroll
    for (int mt = 0; mt < 4; mt++) {
        int r0 = m0 + wm * 64 + mt * 16 + g;
#pragma unroll
        for (int nt = 0; nt < 4; nt++) {
            int c = n0 + wn * 32 + nt * 8 + 2 * tig;
            float2 bv = *reinterpret_cast<const float2*>(bias + c);
            float lox = acc[mt][nt][0] + bv.x, loy = acc[mt][nt][1] + bv.y;
            float hix = acc[mt][nt][2] + bv.x, hiy = acc[mt][nt][3] + bv.y;
            if (mode == 1) {
                float2 rl = *reinterpret_cast<const float2*>(resid + (size_t)r0 * Dm + c);
                float2 rh = *reinterpret_cast<const float2*>(resid + (size_t)(r0 + 8) * Dm + c);
                *reinterpret_cast<float2*>(outf + (size_t)r0 * Dm + c) =
                    make_float2(lox + rl.x, loy + rl.y);
                *reinterpret_cast<float2*>(outf + (size_t)(r0 + 8) * Dm + c) =
                    make_float2(hix + rh.x, hiy + rh.y);
            } else {
                int h = c >> 6, d = c & 63;
                int b0 = r0 >> 11, s0 = r0 & (Sseq - 1);
                size_t o0 = (((size_t)(b0 * Hh + h) * Sseq) + s0) * HD + d;
                *reinterpret_cast<__half2*>(outh + o0) = __floats2half2_rn(lox, loy);
                *reinterpret_cast<__half2*>(outh + o0 + 8 * HD) = __floats2half2_rn(hix, hiy);
            }
        }
    }
}

// ============================================================================
// Kernel 3: fp16 flash attention. 128q x 64k tiles; warp owns 16 q rows.
//   Tiles padded to 72 halves/row (144B) -> conflict-free LDSM.
//   K/V cp.async double-buffered. P round-trips through smem as fp16.
// ============================================================================
#define QS_OFF  0
#define KS_OFF  (128 * 72)              // 2 buffers of 64*72
#define VS_OFF  (KS_OFF + 2 * 64 * 72)
#define PS_OFF  (VS_OFF + 2 * 64 * 72)
#define ATTN_SMEM_HALVES (PS_OFF + 128 * 72)

__global__ __launch_bounds__(256, 2) void attn_h(
    const __half* __restrict__ Q, const __half* __restrict__ K,
    const __half* __restrict__ V, __half* __restrict__ O)
{
    extern __shared__ __align__(16) __half hs[];
    __half* Qs = hs + QS_OFF;
    __half* Ks = hs + KS_OFF;
    __half* Vs = hs + VS_OFF;
    __half* Ps = hs + PS_OFF;

    int tid  = threadIdx.x;
    int lane = tid & 31;
    int warp = tid >> 5;
    int g    = lane >> 2;
    int tig  = lane & 3;
    int bh   = blockIdx.y;
    int q0   = blockIdx.x * 128;
    int qrow = warp * 16 + g;

    const __half* Qb = Q + (size_t)bh * Sseq * HD;
    const __half* Kb = K + (size_t)bh * Sseq * HD;
    const __half* Vb = V + (size_t)bh * Sseq * HD;

    // prologue: stage Q tile + K/V tile 0 (one group)
#pragma unroll
    for (int i = 0; i < 4; i++) {
        int f = tid + 256 * i;          // 0..1023
        int row = f >> 3, c = f & 7;
        CP16(sptr(&Qs[row * 72 + c * 8]), Qb + (size_t)(q0 + row) * HD + c * 8);
    }
#pragma unroll
    for (int i = 0; i < 2; i++) {
        int f = tid + 256 * i;          // 0..511
        int row = f >> 3, c = f & 7;
        CP16(sptr(&Ks[row * 72 + c * 8]), Kb + (size_t)row * HD + c * 8);
        CP16(sptr(&Vs[row * 72 + c * 8]), Vb + (size_t)row * HD + c * 8);
    }
    CP_COMMIT();

    float m0r = -1e30f, m1r = -1e30f, l0 = 0.0f, l1 = 0.0f;
    float o[8][4];
#pragma unroll
    for (int i = 0; i < 8; i++)
#pragma unroll
        for (int j = 0; j < 4; j++) o[i][j] = 0.0f;

    for (int kt = 0; kt < Sseq / 64; kt++) {
        int p = kt & 1;
        CP_WAIT0();
        __syncthreads();
        if (kt < Sseq / 64 - 1) {
            int k1 = (kt + 1) * 64;
            int pn = p ^ 1;
#pragma unroll
            for (int i = 0; i < 2; i++) {
                int f = tid + 256 * i;
                int row = f >> 3, c = f & 7;
                CP16(sptr(&Ks[(pn * 64 + row) * 72 + c * 8]),
                     Kb + (size_t)(k1 + row) * HD + c * 8);
                CP16(sptr(&Vs[(pn * 64 + row) * 72 + c * 8]),
                     Vb + (size_t)(k1 + row) * HD + c * 8);
            }
            CP_COMMIT();
        }

        const __half* Kp = Ks + p * 64 * 72;
        const __half* Vp = Vs + p * 64 * 72;

        // ---- S = Q @ K^T (16 x 64 per warp) ----
        float s[8][4];
#pragma unroll
        for (int nt = 0; nt < 8; nt++)
#pragma unroll
            for (int j = 0; j < 4; j++) s[nt][j] = 0.0f;

        unsigned qa_base = sptr(&Qs[(warp * 16 + (lane & 15)) * 72 + (lane >> 4) * 8]);
        unsigned kb_base = sptr(&Kp[((lane & 7) + ((lane & 16) >> 1)) * 72 + (lane & 8)]);
#pragma unroll
        for (int ks = 0; ks < 4; ks++) {
            unsigned a0, a1, a2, a3;
            ldsm4(a0, a1, a2, a3, qa_base + (ks * 16) * 2);
#pragma unroll
            for (int j = 0; j < 4; j++) {
                unsigned r0, r1, r2, r3;
                ldsm4(r0, r1, r2, r3, kb_base + (j * 16 * 72 + ks * 16) * 2);
                hmma(s[2*j][0], s[2*j][1], s[2*j][2], s[2*j][3], a0, a1, a2, a3, r0, r1);
                hmma(s[2*j+1][0], s[2*j+1][1], s[2*j+1][2], s[2*j+1][3], a0, a1, a2, a3, r2, r3);
            }
        }
        // scale
#pragma unroll
        for (int nt = 0; nt < 8; nt++)
#pragma unroll
            for (int j = 0; j < 4; j++) s[nt][j] *= 0.125f;

        // ---- online softmax (rows qrow, qrow+8) ----
        float rmax0 = -1e30f, rmax1 = -1e30f;
#pragma unroll
        for (int nt = 0; nt < 8; nt++) {
            rmax0 = fmaxf(rmax0, fmaxf(s[nt][0], s[nt][1]));
            rmax1 = fmaxf(rmax1, fmaxf(s[nt][2], s[nt][3]));
        }
        rmax0 = fmaxf(rmax0, __shfl_xor_sync(0xffffffffu, rmax0, 1));
        rmax0 = fmaxf(rmax0, __shfl_xor_sync(0xffffffffu, rmax0, 2));
        rmax1 = fmaxf(rmax1, __shfl_xor_sync(0xffffffffu, rmax1, 1));
        rmax1 = fmaxf(rmax1, __shfl_xor_sync(0xffffffffu, rmax1, 2));
        float mn0 = fmaxf(m0r, rmax0), mn1 = fmaxf(m1r, rmax1);
        float cf0 = __expf(m0r - mn0), cf1 = __expf(m1r - mn1);
        m0r = mn0; m1r = mn1;
        float rs0 = 0.0f, rs1 = 0.0f;
#pragma unroll
        for (int nt = 0; nt < 8; nt++) {
            s[nt][0] = __expf(s[nt][0] - mn0);
            s[nt][1] = __expf(s[nt][1] - mn0);
            s[nt][2] = __expf(s[nt][2] - mn1);
            s[nt][3] = __expf(s[nt][3] - mn1);
            rs0 += s[nt][0] + s[nt][1];
            rs1 += s[nt][2] + s[nt][3];
        }
        rs0 += __shfl_xor_sync(0xffffffffu, rs0, 1);
        rs0 += __shfl_xor_sync(0xffffffffu, rs0, 2);
        rs1 += __shfl_xor_sync(0xffffffffu, rs1, 1);
        rs1 += __shfl_xor_sync(0xffffffffu, rs1, 2);
        l0 = l0 * cf0 + rs0;
        l1 = l1 * cf1 + rs1;
#pragma unroll
        for (int ht = 0; ht < 8; ht++) {
            o[ht][0] *= cf0; o[ht][1] *= cf0;
            o[ht][2] *= cf1; o[ht][3] *= cf1;
        }

        // ---- P -> smem (fp16), warp-private rows ----
#pragma unroll
        for (int nt = 0; nt < 8; nt++) {
            *reinterpret_cast<__half2*>(&Ps[(qrow    ) * 72 + nt * 8 + 2 * tig]) =
                __floats2half2_rn(s[nt][0], s[nt][1]);
            *reinterpret_cast<__half2*>(&Ps[(qrow + 8) * 72 + nt * 8 + 2 * tig]) =
                __floats2half2_rn(s[nt][2], s[nt][3]);
        }
        __syncwarp();

        // ---- O += P @ V ----
        unsigned pa_base = sptr(&Ps[(warp * 16 + (lane & 15)) * 72 + (lane >> 4) * 8]);
        unsigned vb_base = sptr(&Vp[(lane & 15) * 72 + (lane >> 4) * 8]);
#pragma unroll
        for (int ks = 0; ks < 4; ks++) {
            unsigned a0, a1, a2, a3;
            ldsm4(a0, a1, a2, a3, pa_base + (ks * 16) * 2);
#pragma unroll
            for (int j = 0; j < 4; j++) {
                unsigned r0, r1, r2, r3;
                ldsm4t(r0, r1, r2, r3, vb_base + (ks * 16 * 72 + j * 16) * 2);
                hmma(o[2*j][0], o[2*j][1], o[2*j][2], o[2*j][3], a0, a1, a2, a3, r0, r1);
                hmma(o[2*j+1][0], o[2*j+1][1], o[2*j+1][2], o[2*j+1][3], a0, a1, a2, a3, r2, r3);
            }
        }
    }

    // epilogue: normalize, write fp16 token-major
    int b = bh >> 4, h = bh & 15;
    int tok0 = b * Sseq + q0 + qrow;
    float inv0 = 1.0f / l0, inv1 = 1.0f / l1;
#pragma unroll
    for (int ht = 0; ht < 8; ht++) {
        int col = h * HD + ht * 8 + 2 * tig;
        *reinterpret_cast<__half2*>(O + (size_t)tok0 * Dm + col) =
            __floats2half2_rn(o[ht][0] * inv0, o[ht][1] * inv0);
        *reinterpret_cast<__half2*>(O + (size_t)(tok0 + 8) * Dm + col) =
            __floats2half2_rn(o[ht][2] * inv1, o[ht][3] * inv1);
    }
}

// ============================================================================
// Kernel 4: LayerNorm per token
// ============================================================================
__global__ __launch_bounds__(256) void ln_kernel(
    const float* __restrict__ hb, const float* __restrict__ gamma,
    const float* __restrict__ beta, float* __restrict__ out)
{
    int t = blockIdx.x;
    int tid = threadIdx.x;
    __shared__ float red[8];

    float4 v = reinterpret_cast<const float4*>(hb + (size_t)t * Dm)[tid];

    float s = v.x + v.y + v.z + v.w;
    for (int off = 16; off; off >>= 1) s += __shfl_xor_sync(0xffffffffu, s, off);
    if ((tid & 31) == 0) red[tid >> 5] = s;
    __syncthreads();
    float tot = 0.0f;
#pragma unroll
    for (int i = 0; i < 8; i++) tot += red[i];
    float mu = tot * (1.0f / Dm);
    __syncthreads();

    float dx = v.x - mu, dy = v.y - mu, dz = v.z - mu, dw = v.w - mu;
    float sq = dx * dx + dy * dy + dz * dz + dw * dw;
    for (int off = 16; off; off >>= 1) sq += __shfl_xor_sync(0xffffffffu, sq, off);
    if ((tid & 31) == 0) red[tid >> 5] = sq;
    __syncthreads();
    float vtot = 0.0f;
#pragma unroll
    for (int i = 0; i < 8; i++) vtot += red[i];
    float rsd = rsqrtf(vtot * (1.0f / Dm) + 1e-5f);

    int c = tid * 4;
    float4 gm = *reinterpret_cast<const float4*>(gamma + c);
    float4 bt = *reinterpret_cast<const float4*>(beta + c);
    float4 r;
    r.x = dx * rsd * gm.x + bt.x;
    r.y = dy * rsd * gm.y + bt.y;
    r.z = dz * rsd * gm.z + bt.z;
    r.w = dw * rsd * gm.w + bt.w;
    reinterpret_cast<float4*>(out + (size_t)t * Dm)[tid] = r;
}

// ============================================================================
// launch
// ============================================================================
extern "C" void kernel_launch(void* const* d_in, const int* in_sizes, int n_in,
                              void* d_out, int out_size)
{
    const float* x     = (const float*)d_in[0];
    const float* wq    = (const float*)d_in[1];
    const float* bq    = (const float*)d_in[2];
    const float* wk    = (const float*)d_in[3];
    const float* bk    = (const float*)d_in[4];
    const float* wv    = (const float*)d_in[5];
    const float* bv    = (const float*)d_in[6];
    const float* wo    = (const float*)d_in[7];
    const float* bo    = (const float*)d_in[8];
    const float* gamma = (const float*)d_in[9];
    const float* beta  = (const float*)d_in[10];
    const float* pe    = (const float*)d_in[11];
    float* out = (float*)d_out;

    float  *xp, *hb;
    __half *xph, *wh, *qh, *kh, *vh, *oh;
    cudaGetSymbolAddress((void**)&xp,  g_xp);
    cudaGetSymbolAddress((void**)&xph, g_xph);
    cudaGetSymbolAddress((void**)&wh,  g_wh);
    cudaGetSymbolAddress((void**)&qh,  g_qh);
    cudaGetSymbolAddress((void**)&kh,  g_kh);
    cudaGetSymbolAddress((void**)&vh,  g_vh);
    cudaGetSymbolAddress((void**)&oh,  g_oh);
    cudaGetSymbolAddress((void**)&hb,  g_h);

    static const int attn_smem = ATTN_SMEM_HALVES * 2;
    cudaFuncSetAttribute(attn_h, cudaFuncAttributeMaxDynamicSharedMemorySize, attn_smem);

    // 1. x + pe (fp32 + fp16)
    add_pe_kernel<<<(NT * Dm) / (256 * 4), 256>>>(x, pe, xp, xph);

    // 2. weights -> fp16
    int cvt_blocks = (Dm * Dm) / (256 * 8);   // 512
    cvt_kernel<<<cvt_blocks, 256>>>(wq, wh + 0 * Dm * Dm);
    cvt_kernel<<<cvt_blocks, 256>>>(wk, wh + 1 * Dm * Dm);
    cvt_kernel<<<cvt_blocks, 256>>>(wv, wh + 2 * Dm * Dm);
    cvt_kernel<<<cvt_blocks, 256>>>(wo, wh + 3 * Dm * Dm);

    // 3. Q, K, V projections (fp16 scatter to head layout)
    dim3 gemm_grid(Dm / 128, NT / 128);   // (8, 64)
    gemm_h<<<gemm_grid, 256>>>(xph, wh + 0 * Dm * Dm, bq, nullptr, qh, nullptr, 0);
    gemm_h<<<gemm_grid, 256>>>(xph, wh + 1 * Dm * Dm, bk, nullptr, kh, nullptr, 0);
    gemm_h<<<gemm_grid, 256>>>(xph, wh + 2 * Dm * Dm, bv, nullptr, vh, nullptr, 0);

    // 4. flash attention
    dim3 attn_grid(Sseq / 128, Bb * Hh);  // (16, 64)
    attn_h<<<attn_grid, 256, attn_smem>>>(qh, kh, vh, oh);

    // 5. output projection + residual (fp32 out)
    gemm_h<<<gemm_grid, 256>>>(oh, wh + 3 * Dm * Dm, bo, xp, nullptr, hb, 1);

    // 6. layernorm
    ln_kernel<<<NT, 256>>>(hb, gamma, beta, out);
}

// round 9
// speedup vs baseline: 2.9799x; 1.6406x over previous
#include <cuda_runtime.h>
#include <cuda_fp16.h>
#include <math.h>

// Problem constants
#define Dm    1024
#define Sseq  2048
#define Bb    4
#define Hh    16
#define HD    64
#define NT    (Bb * Sseq)   // 8192 tokens

// ---------------- scratch (module-static device memory) --------------------
__device__ float  g_xp [NT * Dm];      // x + pe fp32 (residual)
__device__ __half g_xph[NT * Dm];      // x + pe fp16 (GEMM A)
__device__ __half g_wh [4 * Dm * Dm];  // wq,wk,wv,wo fp16
__device__ __half g_qh [NT * Dm];      // Q  [bh][s][hd] fp16
__device__ __half g_kh [NT * Dm];
__device__ __half g_vh [NT * Dm];
__device__ __half g_oh [NT * Dm];      // attn out [token][D] fp16
__device__ float  g_h  [NT * Dm];      // pre-LN fp32

// ---------------- PTX helpers ----------------------------------------------
__device__ __forceinline__ unsigned sptr(const void* p) {
    return (unsigned)__cvta_generic_to_shared(p);
}

#define CP16(dst, src) \
    asm volatile("cp.async.cg.shared.global [%0], [%1], 16;" :: "r"(dst), "l"(src))
#define CP_COMMIT() asm volatile("cp.async.commit_group;")
#define CP_WAIT0()  asm volatile("cp.async.wait_group 0;")

__device__ __forceinline__ void ldsm4(unsigned& r0, unsigned& r1, unsigned& r2, unsigned& r3,
                                      unsigned addr) {
    asm volatile("ldmatrix.sync.aligned.m8n8.x4.shared.b16 {%0,%1,%2,%3}, [%4];"
        : "=r"(r0), "=r"(r1), "=r"(r2), "=r"(r3) : "r"(addr));
}
__device__ __forceinline__ void ldsm4t(unsigned& r0, unsigned& r1, unsigned& r2, unsigned& r3,
                                       unsigned addr) {
    asm volatile("ldmatrix.sync.aligned.m8n8.x4.trans.shared.b16 {%0,%1,%2,%3}, [%4];"
        : "=r"(r0), "=r"(r1), "=r"(r2), "=r"(r3) : "r"(addr));
}
__device__ __forceinline__ void hmma(float& c0, float& c1, float& c2, float& c3,
                                     unsigned a0, unsigned a1, unsigned a2, unsigned a3,
                                     unsigned b0, unsigned b1) {
    asm volatile(
        "mma.sync.aligned.m16n8k16.row.col.f32.f16.f16.f32 "
        "{%0,%1,%2,%3}, {%4,%5,%6,%7}, {%8,%9}, {%0,%1,%2,%3};"
        : "+f"(c0), "+f"(c1), "+f"(c2), "+f"(c3)
        : "r"(a0), "r"(a1), "r"(a2), "r"(a3), "r"(b0), "r"(b1));
}

// ============================================================================
// Kernel 1: xp = x + pe, write fp32 + fp16
// ============================================================================
__global__ __launch_bounds__(256) void add_pe_kernel(
    const float* __restrict__ x, const float* __restrict__ pe,
    float* __restrict__ xp, __half* __restrict__ xph)
{
    int idx = blockIdx.x * 256 + threadIdx.x;
    int e = idx * 4;
    int t = e >> 10;
    int c = e & 1023;
    int s = t & (Sseq - 1);
    float4 xv = *reinterpret_cast<const float4*>(x + e);
    float4 pv = *reinterpret_cast<const float4*>(pe + s * Dm + c);
    xv.x += pv.x; xv.y += pv.y; xv.z += pv.z; xv.w += pv.w;
    *reinterpret_cast<float4*>(xp + e) = xv;
    __half2 h0 = __floats2half2_rn(xv.x, xv.y);
    __half2 h1 = __floats2half2_rn(xv.z, xv.w);
    *reinterpret_cast<__half2*>(xph + e)     = h0;
    *reinterpret_cast<__half2*>(xph + e + 2) = h1;
}

// all 4 weight matrices -> fp16, one launch (512 blocks per matrix)
struct W4 { const float* w[4]; };
__global__ __launch_bounds__(256) void cvt4_kernel(W4 P, __half* __restrict__ out)
{
    int wsel = blockIdx.x >> 9;
    const float* in = P.w[wsel];
    int i = ((blockIdx.x & 511) * 256 + threadIdx.x) * 8;
    float4 a = *reinterpret_cast<const float4*>(in + i);
    float4 b = *reinterpret_cast<const float4*>(in + i + 4);
    __half2 h0 = __floats2half2_rn(a.x, a.y);
    __half2 h1 = __floats2half2_rn(a.z, a.w);
    __half2 h2 = __floats2half2_rn(b.x, b.y);
    __half2 h3 = __floats2half2_rn(b.z, b.w);
    uint4 pk;
    pk.x = *reinterpret_cast<unsigned*>(&h0);
    pk.y = *reinterpret_cast<unsigned*>(&h1);
    pk.z = *reinterpret_cast<unsigned*>(&h2);
    pk.w = *reinterpret_cast<unsigned*>(&h3);
    *reinterpret_cast<uint4*>(out + (size_t)wsel * Dm * Dm + i) = pk;
}

// ============================================================================
// Kernel 2: fp16 GEMM, 128x128 block tile, K=64 per pipeline stage (2 stages).
//   8 warps (warp 64x32), cp.async staging, ldmatrix, mma.m16n8k16.
//   As rows 72 halves (144B), Bs rows 136 halves (272B): conflict-free LDSM.
//   mode 0 (fused QKV): blockIdx.x selects weight/bias/out; fp16 head scatter.
//   mode 1: single W; fp32 token-major + residual.
//   dynamic smem: 2*(128*72) + 2*(64*136) halves = 71680 B.
// ============================================================================
struct QKVPtrs { const float* bias[3]; __half* outh[3]; };

#define GEMM_SMEM_BYTES ((2 * 128 * 72 + 2 * 64 * 136) * 2)

__global__ __launch_bounds__(256, 2) void gemm_h(
    const __half* __restrict__ A, const __half* __restrict__ Wbase,
    QKVPtrs P, const float* __restrict__ resid,
    float* __restrict__ outf, int mode)
{
    extern __shared__ __align__(16) __half gsm[];
    __half* As = gsm;                       // [2][128*72]
    __half* Bs = gsm + 2 * 128 * 72;        // [2][64*136]

    int tid  = threadIdx.x;
    int lane = tid & 31;
    int warp = tid >> 5;
    int g    = lane >> 2;
    int tig  = lane & 3;
    int wm   = warp & 1;
    int wn   = warp >> 1;
    int m0   = blockIdx.y * 128;

    int wsel, n0;
    const __half* W;
    const float* bias;
    if (mode == 0) {
        wsel = blockIdx.x >> 3;
        n0   = (blockIdx.x & 7) * 128;
        W    = Wbase + (size_t)wsel * Dm * Dm;
        bias = P.bias[wsel];
    } else {
        wsel = 0;
        n0   = blockIdx.x * 128;
        W    = Wbase + (size_t)3 * Dm * Dm;
        bias = P.bias[0];
    }

    float acc[4][4][4];
#pragma unroll
    for (int i = 0; i < 4; i++)
#pragma unroll
        for (int j = 0; j < 4; j++)
#pragma unroll
            for (int r = 0; r < 4; r++) acc[i][j][r] = 0.0f;

#define STAGE(IT, PB)                                                          \
    {                                                                          \
        int kk0 = (IT) * 64;                                                   \
        _Pragma("unroll")                                                      \
        for (int i = 0; i < 4; i++) {                                          \
            int f = tid + 256 * i;                                             \
            int row = f >> 3, c = f & 7;                                       \
            CP16(sptr(&As[(PB) * 9216 + row * 72 + c * 8]),                    \
                 A + (size_t)(m0 + row) * 1024 + kk0 + c * 8);                 \
        }                                                                      \
        _Pragma("unroll")                                                      \
        for (int i = 0; i < 4; i++) {                                          \
            int f = tid + 256 * i;                                             \
            int row = f >> 4, c = f & 15;                                      \
            CP16(sptr(&Bs[(PB) * 8704 + row * 136 + c * 8]),                   \
                 W + (size_t)(kk0 + row) * 1024 + n0 + c * 8);                 \
        }                                                                      \
        CP_COMMIT();                                                           \
    }

    STAGE(0, 0);

    for (int it = 0; it < 16; ++it) {
        int p = it & 1;
        CP_WAIT0();
        __syncthreads();
        if (it < 15) STAGE(it + 1, p ^ 1);

        unsigned a_base = sptr(&As[p * 9216 + (wm * 64 + (lane & 15)) * 72 + (lane >> 4) * 8]);
        unsigned b_base = sptr(&Bs[p * 8704 + (lane & 15) * 136 + wn * 32 + (lane >> 4) * 8]);
#pragma unroll
        for (int ks = 0; ks < 4; ks++) {
            unsigned a[4][4];
#pragma unroll
            for (int mt = 0; mt < 4; mt++)
                ldsm4(a[mt][0], a[mt][1], a[mt][2], a[mt][3],
                      a_base + (mt * 16 * 72 + ks * 16) * 2);
#pragma unroll
            for (int j = 0; j < 2; j++) {
                unsigned r0, r1, r2, r3;
                ldsm4t(r0, r1, r2, r3, b_base + (ks * 16 * 136 + j * 16) * 2);
#pragma unroll
                for (int mt = 0; mt < 4; mt++) {
                    hmma(acc[mt][2*j][0], acc[mt][2*j][1], acc[mt][2*j][2], acc[mt][2*j][3],
                         a[mt][0], a[mt][1], a[mt][2], a[mt][3], r0, r1);
                    hmma(acc[mt][2*j+1][0], acc[mt][2*j+1][1], acc[mt][2*j+1][2], acc[mt][2*j+1][3],
                         a[mt][0], a[mt][1], a[mt][2], a[mt][3], r2, r3);
                }
            }
        }
    }
#undef STAGE

    // epilogue
    __half* outh = (mode == 0) ? P.outh[wsel] : nullptr;
#pragma unroll
    for (int mt = 0; mt < 4; mt++) {
        int r0 = m0 + wm * 64 + mt * 16 + g;
#pragma unroll
        for (int nt = 0; nt < 4; nt++) {
            int c = n0 + wn * 32 + nt * 8 + 2 * tig;
            float2 bv = *reinterpret_cast<const float2*>(bias + c);
            float lox = acc[mt][nt][0] + bv.x, loy = acc[mt][nt][1] + bv.y;
            float hix = acc[mt][nt][2] + bv.x, hiy = acc[mt][nt][3] + bv.y;
            if (mode == 1) {
                float2 rl = *reinterpret_cast<const float2*>(resid + (size_t)r0 * Dm + c);
                float2 rh = *reinterpret_cast<const float2*>(resid + (size_t)(r0 + 8) * Dm + c);
                *reinterpret_cast<float2*>(outf + (size_t)r0 * Dm + c) =
                    make_float2(lox + rl.x, loy + rl.y);
                *reinterpret_cast<float2*>(outf + (size_t)(r0 + 8) * Dm + c) =
                    make_float2(hix + rh.x, hiy + rh.y);
            } else {
                int h = c >> 6, d = c & 63;
                int b0 = r0 >> 11, s0 = r0 & (Sseq - 1);
                size_t o0 = (((size_t)(b0 * Hh + h) * Sseq) + s0) * HD + d;
                *reinterpret_cast<__half2*>(outh + o0) = __floats2half2_rn(lox, loy);
                *reinterpret_cast<__half2*>(outh + o0 + 8 * HD) = __floats2half2_rn(hix, hiy);
            }
        }
    }
}

// ============================================================================
// Kernel 3: fp16 flash attention. 128q x 64k tiles; warp owns 16 q rows.
//   exp2-folded softmax: scores scaled by 0.125*log2(e), probs via exp2f.
// ============================================================================
#define QS_OFF  0
#define KS_OFF  (128 * 72)              // 2 buffers of 64*72
#define VS_OFF  (KS_OFF + 2 * 64 * 72)
#define PS_OFF  (VS_OFF + 2 * 64 * 72)
#define ATTN_SMEM_HALVES (PS_OFF + 128 * 72)
#define SM_SCALE (0.125f * 1.44269504088896f)   // 1/sqrt(64) * log2(e)

__global__ __launch_bounds__(256, 2) void attn_h(
    const __half* __restrict__ Q, const __half* __restrict__ K,
    const __half* __restrict__ V, __half* __restrict__ O)
{
    extern __shared__ __align__(16) __half hs[];
    __half* Qs = hs + QS_OFF;
    __half* Ks = hs + KS_OFF;
    __half* Vs = hs + VS_OFF;
    __half* Ps = hs + PS_OFF;

    int tid  = threadIdx.x;
    int lane = tid & 31;
    int warp = tid >> 5;
    int g    = lane >> 2;
    int tig  = lane & 3;
    int bh   = blockIdx.y;
    int q0   = blockIdx.x * 128;
    int qrow = warp * 16 + g;

    const __half* Qb = Q + (size_t)bh * Sseq * HD;
    const __half* Kb = K + (size_t)bh * Sseq * HD;
    const __half* Vb = V + (size_t)bh * Sseq * HD;

    // prologue: stage Q tile + K/V tile 0
#pragma unroll
    for (int i = 0; i < 4; i++) {
        int f = tid + 256 * i;
        int row = f >> 3, c = f & 7;
        CP16(sptr(&Qs[row * 72 + c * 8]), Qb + (size_t)(q0 + row) * HD + c * 8);
    }
#pragma unroll
    for (int i = 0; i < 2; i++) {
        int f = tid + 256 * i;
        int row = f >> 3, c = f & 7;
        CP16(sptr(&Ks[row * 72 + c * 8]), Kb + (size_t)row * HD + c * 8);
        CP16(sptr(&Vs[row * 72 + c * 8]), Vb + (size_t)row * HD + c * 8);
    }
    CP_COMMIT();

    float m0r = -1e30f, m1r = -1e30f, l0 = 0.0f, l1 = 0.0f;
    float o[8][4];
#pragma unroll
    for (int i = 0; i < 8; i++)
#pragma unroll
        for (int j = 0; j < 4; j++) o[i][j] = 0.0f;

    for (int kt = 0; kt < Sseq / 64; kt++) {
        int p = kt & 1;
        CP_WAIT0();
        __syncthreads();
        if (kt < Sseq / 64 - 1) {
            int k1 = (kt + 1) * 64;
            int pn = p ^ 1;
#pragma unroll
            for (int i = 0; i < 2; i++) {
                int f = tid + 256 * i;
                int row = f >> 3, c = f & 7;
                CP16(sptr(&Ks[(pn * 64 + row) * 72 + c * 8]),
                     Kb + (size_t)(k1 + row) * HD + c * 8);
                CP16(sptr(&Vs[(pn * 64 + row) * 72 + c * 8]),
                     Vb + (size_t)(k1 + row) * HD + c * 8);
            }
            CP_COMMIT();
        }

        const __half* Kp = Ks + p * 64 * 72;
        const __half* Vp = Vs + p * 64 * 72;

        // ---- S = Q @ K^T (16 x 64 per warp) ----
        float s[8][4];
#pragma unroll
        for (int nt = 0; nt < 8; nt++)
#pragma unroll
            for (int j = 0; j < 4; j++) s[nt][j] = 0.0f;

        unsigned qa_base = sptr(&Qs[(warp * 16 + (lane & 15)) * 72 + (lane >> 4) * 8]);
        unsigned kb_base = sptr(&Kp[((lane & 7) + ((lane & 16) >> 1)) * 72 + (lane & 8)]);
#pragma unroll
        for (int ks = 0; ks < 4; ks++) {
            unsigned a0, a1, a2, a3;
            ldsm4(a0, a1, a2, a3, qa_base + (ks * 16) * 2);
#pragma unroll
            for (int j = 0; j < 4; j++) {
                unsigned r0, r1, r2, r3;
                ldsm4(r0, r1, r2, r3, kb_base + (j * 16 * 72 + ks * 16) * 2);
                hmma(s[2*j][0], s[2*j][1], s[2*j][2], s[2*j][3], a0, a1, a2, a3, r0, r1);
                hmma(s[2*j+1][0], s[2*j+1][1], s[2*j+1][2], s[2*j+1][3], a0, a1, a2, a3, r2, r3);
            }
        }
        // scale into log2 domain (folds softmax scale + log2e)
#pragma unroll
        for (int nt = 0; nt < 8; nt++)
#pragma unroll
            for (int j = 0; j < 4; j++) s[nt][j] *= SM_SCALE;

        // ---- online softmax (rows qrow, qrow+8), exp2 domain ----
        float rmax0 = -1e30f, rmax1 = -1e30f;
#pragma unroll
        for (int nt = 0; nt < 8; nt++) {
            rmax0 = fmaxf(rmax0, fmaxf(s[nt][0], s[nt][1]));
            rmax1 = fmaxf(rmax1, fmaxf(s[nt][2], s[nt][3]));
        }
        rmax0 = fmaxf(rmax0, __shfl_xor_sync(0xffffffffu, rmax0, 1));
        rmax0 = fmaxf(rmax0, __shfl_xor_sync(0xffffffffu, rmax0, 2));
        rmax1 = fmaxf(rmax1, __shfl_xor_sync(0xffffffffu, rmax1, 1));
        rmax1 = fmaxf(rmax1, __shfl_xor_sync(0xffffffffu, rmax1, 2));
        float mn0 = fmaxf(m0r, rmax0), mn1 = fmaxf(m1r, rmax1);
        float cf0 = exp2f(m0r - mn0), cf1 = exp2f(m1r - mn1);
        m0r = mn0; m1r = mn1;
        float rs0 = 0.0f, rs1 = 0.0f;
#pragma unroll
        for (int nt = 0; nt < 8; nt++) {
            s[nt][0] = exp2f(s[nt][0] - mn0);
            s[nt][1] = exp2f(s[nt][1] - mn0);
            s[nt][2] = exp2f(s[nt][2] - mn1);
            s[nt][3] = exp2f(s[nt][3] - mn1);
            rs0 += s[nt][0] + s[nt][1];
            rs1 += s[nt][2] + s[nt][3];
        }
        rs0 += __shfl_xor_sync(0xffffffffu, rs0, 1);
        rs0 += __shfl_xor_sync(0xffffffffu, rs0, 2);
        rs1 += __shfl_xor_sync(0xffffffffu, rs1, 1);
        rs1 += __shfl_xor_sync(0xffffffffu, rs1, 2);
        l0 = l0 * cf0 + rs0;
        l1 = l1 * cf1 + rs1;
#pragma unroll
        for (int ht = 0; ht < 8; ht++) {
            o[ht][0] *= cf0; o[ht][1] *= cf0;
            o[ht][2] *= cf1; o[ht][3] *= cf1;
        }

        // ---- P -> smem (fp16), warp-private rows ----
#pragma unroll
        for (int nt = 0; nt < 8; nt++) {
            *reinterpret_cast<__half2*>(&Ps[(qrow    ) * 72 + nt * 8 + 2 * tig]) =
                __floats2half2_rn(s[nt][0], s[nt][1]);
            *reinterpret_cast<__half2*>(&Ps[(qrow + 8) * 72 + nt * 8 + 2 * tig]) =
                __floats2half2_rn(s[nt][2], s[nt][3]);
        }
        __syncwarp();

        // ---- O += P @ V ----
        unsigned pa_base = sptr(&Ps[(warp * 16 + (lane & 15)) * 72 + (lane >> 4) * 8]);
        unsigned vb_base = sptr(&Vp[(lane & 15) * 72 + (lane >> 4) * 8]);
#pragma unroll
        for (int ks = 0; ks < 4; ks++) {
            unsigned a0, a1, a2, a3;
            ldsm4(a0, a1, a2, a3, pa_base + (ks * 16) * 2);
#pragma unroll
            for (int j = 0; j < 4; j++) {
                unsigned r0, r1, r2, r3;
                ldsm4t(r0, r1, r2, r3, vb_base + (ks * 16 * 72 + j * 16) * 2);
                hmma(o[2*j][0], o[2*j][1], o[2*j][2], o[2*j][3], a0, a1, a2, a3, r0, r1);
                hmma(o[2*j+1][0], o[2*j+1][1], o[2*j+1][2], o[2*j+1][3], a0, a1, a2, a3, r2, r3);
            }
        }
    }

    // epilogue: normalize, write fp16 token-major
    int b = bh >> 4, h = bh & 15;
    int tok0 = b * Sseq + q0 + qrow;
    float inv0 = 1.0f / l0, inv1 = 1.0f / l1;
#pragma unroll
    for (int ht = 0; ht < 8; ht++) {
        int col = h * HD + ht * 8 + 2 * tig;
        *reinterpret_cast<__half2*>(O + (size_t)tok0 * Dm + col) =
            __floats2half2_rn(o[ht][0] * inv0, o[ht][1] * inv0);
        *reinterpret_cast<__half2*>(O + (size_t)(tok0 + 8) * Dm + col) =
            __floats2half2_rn(o[ht][2] * inv1, o[ht][3] * inv1);
    }
}

// ============================================================================
// Kernel 4: LayerNorm per token
// ============================================================================
__global__ __launch_bounds__(256) void ln_kernel(
    const float* __restrict__ hb, const float* __restrict__ gamma,
    const float* __restrict__ beta, float* __restrict__ out)
{
    int t = blockIdx.x;
    int tid = threadIdx.x;
    __shared__ float red[8];

    float4 v = reinterpret_cast<const float4*>(hb + (size_t)t * Dm)[tid];

    float s = v.x + v.y + v.z + v.w;
    for (int off = 16; off; off >>= 1) s += __shfl_xor_sync(0xffffffffu, s, off);
    if ((tid & 31) == 0) red[tid >> 5] = s;
    __syncthreads();
    float tot = 0.0f;
#pragma unroll
    for (int i = 0; i < 8; i++) tot += red[i];
    float mu = tot * (1.0f / Dm);
    __syncthreads();

    float dx = v.x - mu, dy = v.y - mu, dz = v.z - mu, dw = v.w - mu;
    float sq = dx * dx + dy * dy + dz * dz + dw * dw;
    for (int off = 16; off; off >>= 1) sq += __shfl_xor_sync(0xffffffffu, sq, off);
    if ((tid & 31) == 0) red[tid >> 5] = sq;
    __syncthreads();
    float vtot = 0.0f;
#pragma unroll
    for (int i = 0; i < 8; i++) vtot += red[i];
    float rsd = rsqrtf(vtot * (1.0f / Dm) + 1e-5f);

    int c = tid * 4;
    float4 gm = *reinterpret_cast<const float4*>(gamma + c);
    float4 bt = *reinterpret_cast<const float4*>(beta + c);
    float4 r;
    r.x = dx * rsd * gm.x + bt.x;
    r.y = dy * rsd * gm.y + bt.y;
    r.z = dz * rsd * gm.z + bt.z;
    r.w = dw * rsd * gm.w + bt.w;
    reinterpret_cast<float4*>(out + (size_t)t * Dm)[tid] = r;
}

// ============================================================================
// launch
// ============================================================================
extern "C" void kernel_launch(void* const* d_in, const int* in_sizes, int n_in,
                              void* d_out, int out_size)
{
    const float* x     = (const float*)d_in[0];
    const float* wq    = (const float*)d_in[1];
    const float* bq    = (const float*)d_in[2];
    const float* wk    = (const float*)d_in[3];
    const float* bk    = (const float*)d_in[4];
    const float* wv    = (const float*)d_in[5];
    const float* bv    = (const float*)d_in[6];
    const float* wo    = (const float*)d_in[7];
    const float* bo    = (const float*)d_in[8];
    const float* gamma = (const float*)d_in[9];
    const float* beta  = (const float*)d_in[10];
    const float* pe    = (const float*)d_in[11];
    float* out = (float*)d_out;

    float  *xp, *hb;
    __half *xph, *wh, *qh, *kh, *vh, *oh;
    cudaGetSymbolAddress((void**)&xp,  g_xp);
    cudaGetSymbolAddress((void**)&xph, g_xph);
    cudaGetSymbolAddress((void**)&wh,  g_wh);
    cudaGetSymbolAddress((void**)&qh,  g_qh);
    cudaGetSymbolAddress((void**)&kh,  g_kh);
    cudaGetSymbolAddress((void**)&vh,  g_vh);
    cudaGetSymbolAddress((void**)&oh,  g_oh);
    cudaGetSymbolAddress((void**)&hb,  g_h);

    static const int attn_smem = ATTN_SMEM_HALVES * 2;
    cudaFuncSetAttribute(attn_h, cudaFuncAttributeMaxDynamicSharedMemorySize, attn_smem);
    cudaFuncSetAttribute(gemm_h, cudaFuncAttributeMaxDynamicSharedMemorySize, GEMM_SMEM_BYTES);

    // 1. x + pe (fp32 + fp16)
    add_pe_kernel<<<(NT * Dm) / (256 * 4), 256>>>(x, pe, xp, xph);

    // 2. all weights -> fp16, one launch
    W4 w4; w4.w[0] = wq; w4.w[1] = wk; w4.w[2] = wv; w4.w[3] = wo;
    cvt4_kernel<<<2048, 256>>>(w4, wh);

    // 3. fused QKV projection (one launch, 24 n-blocks)
    QKVPtrs qkv;
    qkv.bias[0] = bq; qkv.bias[1] = bk; qkv.bias[2] = bv;
    qkv.outh[0] = qh; qkv.outh[1] = kh; qkv.outh[2] = vh;
    dim3 qkv_grid(24, NT / 128);
    gemm_h<<<qkv_grid, 256, GEMM_SMEM_BYTES>>>(xph, wh, qkv, nullptr, nullptr, 0);

    // 4. flash attention
    dim3 attn_grid(Sseq / 128, Bb * Hh);  // (16, 64)
    attn_h<<<attn_grid, 256, attn_smem>>>(qh, kh, vh, oh);

    // 5. output projection + residual (fp32 out)
    QKVPtrs op;
    op.bias[0] = bo; op.bias[1] = bo; op.bias[2] = bo;
    op.outh[0] = nullptr; op.outh[1] = nullptr; op.outh[2] = nullptr;
    dim3 out_grid(Dm / 128, NT / 128);
    gemm_h<<<out_grid, 256, GEMM_SMEM_BYTES>>>(oh, wh, op, xp, hb, 1);

    // 6. layernorm
    ln_kernel<<<NT, 256>>>(hb, gamma, beta, out);
}